// round 9
// baseline (speedup 1.0000x reference)
#include <cuda_runtime.h>
#include <math.h>
#include <stdint.h>

// DPLSTMCell row-0, R9: 3-deep software pipeline (R8 was 2-deep).
// grid=296 (2 blocks/SM), 256 threads; block handles n = bid + 296*it, it=0..3.
// Triple-buffered cp.async (3 x 32KB smem, wait_group 2): TWO 32KB groups in flight
// per block during the wait -> 128KB outstanding per SM (was 64KB). Vectors x/h in
// registers, reused across iterations. MUFU fast epilogue (R7-proven).

#define H 1024
#define D 1024
#define NBLK 296
#define NIT 4
#define DEPTH 3

__device__ __forceinline__ float warp_reduce(float v) {
    #pragma unroll
    for (int off = 16; off > 0; off >>= 1)
        v += __shfl_xor_sync(0xFFFFFFFFu, v, off);
    return v;
}

__device__ __forceinline__ float fast_tanh(float x) {
    float r;
    asm("tanh.approx.f32 %0, %1;" : "=f"(r) : "f"(x));
    return r;
}
__device__ __forceinline__ float fast_sigmoid(float x) {
    return 0.5f * fast_tanh(0.5f * x) + 0.5f;
}

__global__ __launch_bounds__(256)
void lstm_row0_pipe3_kernel(const float* __restrict__ x,
                            const float* __restrict__ h,
                            const float* __restrict__ c_prev,
                            const float* __restrict__ Wih,
                            const float* __restrict__ Whh,
                            const float* __restrict__ bih,
                            const float* __restrict__ bhh,
                            float* __restrict__ out) {
    extern __shared__ float4 buf[];          // [DEPTH][8 rows][256 float4] = 3 x 32KB
    __shared__ float sums[DEPTH][8];

    const int bid  = blockIdx.x;
    const int tid  = threadIdx.x;
    const int wid  = tid >> 5;               // row 0..7: gate = wid>>1, mat = wid&1
    const int lane = tid & 31;
    const int mat  = wid & 1;

    // Preload this warp's vector (x or h) into registers: 8 float4/lane, reused 4x.
    const float4* __restrict__ v4 = reinterpret_cast<const float4*>(mat ? h : x);
    float4 vr[8];
    #pragma unroll
    for (int i = 0; i < 8; i++)
        vr[i] = v4[lane + i * 32];

    // Issue weight loads for iteration 'it' into buf[it % DEPTH].
    auto issue = [&](int it) {
        const int n = bid + NBLK * it;
        if (it < NIT && n < H) {
            float4* dst4 = &buf[(it % DEPTH) * 2048];
            #pragma unroll
            for (int r = 0; r < 8; r++) {
                const int g = r >> 1;
                const int m = r & 1;
                const float* src = (m ? Whh : Wih) + (size_t)(g * H + n) * D + tid * 4;
                const uint32_t dst =
                    (uint32_t)__cvta_generic_to_shared(&dst4[r * 256 + tid]);
                asm volatile("cp.async.cg.shared.global [%0], [%1], 16;"
                             :: "r"(dst), "l"(src) : "memory");
            }
        }
        asm volatile("cp.async.commit_group;" ::: "memory");  // uniform group count
    };

    issue(0);
    issue(1);
    issue(2);

    #pragma unroll
    for (int it = 0; it < NIT; it++) {
        const int n = bid + NBLK * it;
        const int b = it % DEPTH;

        asm volatile("cp.async.wait_group %0;" :: "n"(DEPTH - 1) : "memory");
        __syncthreads();

        if (n < H) {
            const float4* w4 = &buf[b * 2048 + wid * 256];
            float acc = 0.0f;
            #pragma unroll
            for (int i = 0; i < 8; i++) {
                const float4 wv = w4[lane + i * 32];
                acc += wv.x * vr[i].x + wv.y * vr[i].y
                     + wv.z * vr[i].z + wv.w * vr[i].w;
            }
            acc = warp_reduce(acc);
            if (lane == 0) sums[b][wid] = acc;
        }
        __syncthreads();   // all reads of buf[b] done; sums[b] visible

        issue(it + DEPTH); // refill buf[b] ASAP (before epilogue)

        if (tid == 0 && n < H) {
            float gi = sums[b][0] + sums[b][1] + bih[n]         + bhh[n];
            float gf = sums[b][2] + sums[b][3] + bih[H + n]     + bhh[H + n];
            float gg = sums[b][4] + sums[b][5] + bih[2 * H + n] + bhh[2 * H + n];
            float go = sums[b][6] + sums[b][7] + bih[3 * H + n] + bhh[3 * H + n];

            float i_t = fast_sigmoid(gi);
            float f_t = fast_sigmoid(gf);
            float g_t = fast_tanh(gg);
            float o_t = fast_sigmoid(go);

            float c_t = f_t * c_prev[n] + i_t * g_t;
            out[n] = o_t * fast_tanh(c_t);
        }
    }
}

extern "C" void kernel_launch(void* const* d_in, const int* in_sizes, int n_in,
                              void* d_out, int out_size) {
    const float* x      = (const float*)d_in[0];
    const float* h      = (const float*)d_in[1];
    const float* c_prev = (const float*)d_in[2];
    const float* Wih    = (const float*)d_in[3];
    const float* Whh    = (const float*)d_in[4];
    const float* bih    = (const float*)d_in[5];
    const float* bhh    = (const float*)d_in[6];
    float* out = (float*)d_out;

    static int smem_set = 0;
    if (!smem_set) {
        cudaFuncSetAttribute(lstm_row0_pipe3_kernel,
                             cudaFuncAttributeMaxDynamicSharedMemorySize,
                             DEPTH * 32 * 1024);
        smem_set = 1;
    }
    lstm_row0_pipe3_kernel<<<NBLK, 256, DEPTH * 32 * 1024>>>(
        x, h, c_prev, Wih, Whh, bih, bhh, out);
}

// round 10
// speedup vs baseline: 1.2353x; 1.2353x over previous
#include <cuda_runtime.h>
#include <math.h>
#include <stdint.h>

// DPLSTMCell row-0, R10: dual-path memory supply.
// Model from R1-R9: per-SM in-flight line cap (~64-80 lines) bounds each memory path
// at ~20GB/s/SM; LDG and LDGSTS(cp.async) have separate tracking. So split the
// 32KB/block weight stream across BOTH paths concurrently:
//   warps 0-3: Wih rows via plain LDG.128 (R1-proven best warm path)
//   warps 4-7: Whh rows via cp.async.cg -> smem (per-warp wait, no extra barriers)
// Fast MUFU epilogue (R7+). No .nc / evict hints (warm regressions R5/R7).

#define H 1024
#define D 1024

__device__ __forceinline__ float warp_reduce(float v) {
    #pragma unroll
    for (int off = 16; off > 0; off >>= 1)
        v += __shfl_xor_sync(0xFFFFFFFFu, v, off);
    return v;
}

__device__ __forceinline__ float fast_tanh(float x) {
    float r;
    asm("tanh.approx.f32 %0, %1;" : "=f"(r) : "f"(x));
    return r;
}
__device__ __forceinline__ float fast_sigmoid(float x) {
    return 0.5f * fast_tanh(0.5f * x) + 0.5f;
}

__global__ __launch_bounds__(256)
void lstm_row0_dual_kernel(const float* __restrict__ x,
                           const float* __restrict__ h,
                           const float* __restrict__ c_prev,
                           const float* __restrict__ Wih,
                           const float* __restrict__ Whh,
                           const float* __restrict__ bih,
                           const float* __restrict__ bhh,
                           float* __restrict__ out) {
    __shared__ __align__(128) float4 swh[4 * 256];  // 16KB: 4 Whh rows
    __shared__ float sums[8];

    const int n    = blockIdx.x;
    const int tid  = threadIdx.x;
    const int wid  = tid >> 5;
    const int lane = tid & 31;

    float acc = 0.0f;

    if (wid >= 4) {
        // ---- async path: Whh row for gate = wid-4 ----
        const int gate = wid - 4;
        const float* src_base = Whh + (size_t)(gate * H + n) * D;
        #pragma unroll
        for (int i = 0; i < 8; i++) {
            const float* src = src_base + (lane + i * 32) * 4;
            const uint32_t dst = (uint32_t)__cvta_generic_to_shared(
                &swh[gate * 256 + lane + i * 32]);
            asm volatile("cp.async.cg.shared.global [%0], [%1], 16;"
                         :: "r"(dst), "l"(src) : "memory");
        }
        asm volatile("cp.async.commit_group;" ::: "memory");

        // Vector h loads (L1/L2-hot) overlap the async transfer.
        const float4* __restrict__ v4 = reinterpret_cast<const float4*>(h);
        float4 vr[8];
        #pragma unroll
        for (int i = 0; i < 8; i++)
            vr[i] = v4[lane + i * 32];

        asm volatile("cp.async.wait_group 0;" ::: "memory");
        __syncwarp();

        const float4* w4 = &swh[gate * 256];
        #pragma unroll
        for (int i = 0; i < 8; i++) {
            const float4 wv = w4[lane + i * 32];
            acc += wv.x * vr[i].x + wv.y * vr[i].y
                 + wv.z * vr[i].z + wv.w * vr[i].w;
        }
    } else {
        // ---- LDG path: Wih row for gate = wid (exact R1 loop) ----
        const int gate = wid;
        const float4* __restrict__ w4 = reinterpret_cast<const float4*>(
            Wih + (size_t)(gate * H + n) * D);
        const float4* __restrict__ v4 = reinterpret_cast<const float4*>(x);
        #pragma unroll
        for (int i = 0; i < 8; i++) {
            const int idx = lane + i * 32;
            const float4 wv = w4[idx];
            const float4 xv = v4[idx];
            acc += wv.x * xv.x + wv.y * xv.y + wv.z * xv.z + wv.w * xv.w;
        }
    }

    acc = warp_reduce(acc);
    if (lane == 0) sums[wid] = acc;
    __syncthreads();

    if (tid == 0) {
        // sums[g] = Wih·x for gate g ; sums[4+g] = Whh·h for gate g
        float gi = sums[0] + sums[4] + bih[n]         + bhh[n];
        float gf = sums[1] + sums[5] + bih[H + n]     + bhh[H + n];
        float gg = sums[2] + sums[6] + bih[2 * H + n] + bhh[2 * H + n];
        float go = sums[3] + sums[7] + bih[3 * H + n] + bhh[3 * H + n];

        float i_t = fast_sigmoid(gi);
        float f_t = fast_sigmoid(gf);
        float g_t = fast_tanh(gg);
        float o_t = fast_sigmoid(go);

        float c_t = f_t * c_prev[n] + i_t * g_t;
        out[n] = o_t * fast_tanh(c_t);
    }
}

extern "C" void kernel_launch(void* const* d_in, const int* in_sizes, int n_in,
                              void* d_out, int out_size) {
    const float* x      = (const float*)d_in[0];
    const float* h      = (const float*)d_in[1];
    const float* c_prev = (const float*)d_in[2];
    const float* Wih    = (const float*)d_in[3];
    const float* Whh    = (const float*)d_in[4];
    const float* bih    = (const float*)d_in[5];
    const float* bhh    = (const float*)d_in[6];
    float* out = (float*)d_out;

    lstm_row0_dual_kernel<<<H, 256>>>(x, h, c_prev, Wih, Whh, bih, bhh, out);
}